// round 7
// baseline (speedup 1.0000x reference)
#include <cuda_runtime.h>
#include <cstdint>

#define N 2048
#define E 4
#define C 4
#define F 128      // W_OUT
#define WIN 256
#define NNSZ ((size_t)N * N)
#define NFSZ ((size_t)N * F)

// ---------------- scratch (static device globals; no allocation) ----------------
__device__ float g_fw[3][16];            // softmaxed weights: [0]=fw1, [1]=fw2, [2]=fw3
__device__ float g_support[N * F];       // X @ gcn_w              [n][f]
__device__ float g_v1[C * N];
__device__ float g_v2[C * N];
__device__ float g_v3[C * N];
__device__ float g_d[C * N];             // deg^-1/2
__device__ float g_Sp[C * N * F];        // diag(d)@support natural [c][n][f]
__device__ float g_SpB[C * N * F];       // fragment-order B plane (stage 0)
__device__ float g_T0B[C * N * F];       // fragment-order B plane (stage 1)
__device__ float g_T1B[C * N * F];       // fragment-order B plane (stage 2)
// fragment-ordered premixed adjacency planes: [stage*4 + c], unit = m16 x k8 (128 floats)
__device__ float g_Am[12 * NNSZ];

__device__ __forceinline__ float to_tf32(float x) {
    float r; asm("cvt.rna.tf32.f32 %0, %1;" : "=f"(r) : "f"(x)); return r;
}

__device__ __forceinline__ void mma_tf32(float& d0, float& d1, float& d2, float& d3,
                                         uint32_t a0, uint32_t a1, uint32_t a2, uint32_t a3,
                                         uint32_t b0, uint32_t b1) {
    asm volatile(
        "mma.sync.aligned.m16n8k8.row.col.f32.tf32.tf32.f32 "
        "{%0,%1,%2,%3}, {%4,%5,%6,%7}, {%8,%9}, {%0,%1,%2,%3};"
        : "+f"(d0), "+f"(d1), "+f"(d2), "+f"(d3)
        : "r"(a0), "r"(a1), "r"(a2), "r"(a3), "r"(b0), "r"(b1));
}

// ---------------- tiny: softmax of 4x4 weight rows ----------------
__global__ void k_softmax(const float* __restrict__ w1,
                          const float* __restrict__ w2,
                          const float* __restrict__ w3) {
    int t = threadIdx.x;
    if (t >= 12) return;
    int mat = t >> 2, row = t & 3;
    const float* src = (mat == 0) ? w1 : (mat == 1) ? w2 : w3;
    float a0 = src[row * 4 + 0], a1 = src[row * 4 + 1];
    float a2 = src[row * 4 + 2], a3 = src[row * 4 + 3];
    float mx = fmaxf(fmaxf(a0, a1), fmaxf(a2, a3));
    float e0 = expf(a0 - mx), e1 = expf(a1 - mx), e2 = expf(a2 - mx), e3 = expf(a3 - mx);
    float inv = 1.0f / (e0 + e1 + e2 + e3);
    g_fw[mat][row * 4 + 0] = e0 * inv;
    g_fw[mat][row * 4 + 1] = e1 * inv;
    g_fw[mat][row * 4 + 2] = e2 * inv;
    g_fw[mat][row * 4 + 3] = e3 * inv;
}

// ---------------- support = X @ gcn_w ----------------
__global__ void __launch_bounds__(256) k_support(const float* __restrict__ X,
                                                 const float* __restrict__ W) {
    __shared__ float Xs[32][WIN];
    int tid = threadIdx.x;
    int row0 = blockIdx.x * 32;
    const float4* Xg = (const float4*)(X + (size_t)row0 * WIN);
    float4* Xs4 = (float4*)&Xs[0][0];
    #pragma unroll
    for (int j = 0; j < (32 * WIN / 4) / 256; j++)
        Xs4[tid + j * 256] = Xg[tid + j * 256];
    __syncthreads();
    int f = tid & 127, ty = tid >> 7;
    float acc[16];
    #pragma unroll
    for (int r = 0; r < 16; r++) acc[r] = 0.f;
    for (int k = 0; k < WIN; k++) {
        float w = W[k * F + f];
        #pragma unroll
        for (int r = 0; r < 16; r++)
            acc[r] = fmaf(Xs[ty * 16 + r][k], w, acc[r]);
    }
    #pragma unroll
    for (int r = 0; r < 16; r++)
        g_support[(size_t)(row0 + ty * 16 + r) * F + f] = acc[r];
}

// ---------------- rowsums of raw A + fw3-mix -> v1 (chain B head) ----------------
__global__ void __launch_bounds__(256) k_rowsum_mix(const float* __restrict__ A) {
    int n = blockIdx.x;
    int tid = threadIdx.x;
    float s[4] = {0.f, 0.f, 0.f, 0.f};
    #pragma unroll
    for (int it = 0; it < (N / 4) / 256; it++) {
        int m4 = tid + it * 256;
        #pragma unroll
        for (int e = 0; e < 4; e++) {
            float4 v = ((const float4*)(A + (size_t)e * NNSZ + (size_t)n * N))[m4];
            s[e] += v.x + v.y + v.z + v.w;
        }
    }
    #pragma unroll
    for (int off = 16; off > 0; off >>= 1)
        #pragma unroll
        for (int e = 0; e < 4; e++)
            s[e] += __shfl_down_sync(0xffffffffu, s[e], off);
    __shared__ float red[8][4];
    int lane = tid & 31, wid = tid >> 5;
    if (lane == 0) { red[wid][0] = s[0]; red[wid][1] = s[1]; red[wid][2] = s[2]; red[wid][3] = s[3]; }
    __syncthreads();
    if (tid < 4) {
        float r[4];
        #pragma unroll
        for (int e = 0; e < 4; e++) {
            float t = 0.f;
            #pragma unroll
            for (int w = 0; w < 8; w++) t += red[w][e];
            r[e] = t;
        }
        g_v1[tid * N + n] = g_fw[2][tid * 4 + 0] * r[0] + g_fw[2][tid * 4 + 1] * r[1]
                          + g_fw[2][tid * 4 + 2] * r[2] + g_fw[2][tid * 4 + 3] * r[3];
    }
}

// ---------------- premix: one (band, chunk) tile per CTA (chain A) ----------------
__global__ void __launch_bounds__(256) k_premix_f(const float* __restrict__ A) {
    __shared__ float As[4][16][132];
    __shared__ float wsm[48];
    const int tid = threadIdx.x, lane = tid & 31, warp = tid >> 5;
    const int g = lane >> 2, cl = lane & 3;
    const int ch = blockIdx.x;            // 0..15 (128-col chunk)
    const int band = blockIdx.y;          // 0..127 (16-row band)
    const int n0 = band * 16, m0 = ch * 128;

    if (tid < 48) wsm[tid] = ((const float*)g_fw)[tid];
    #pragma unroll
    for (int e = 0; e < 4; e++)
        #pragma unroll
        for (int j = 0; j < 2; j++) {
            int idx = tid + j * 256;
            int r = idx >> 5, m4 = idx & 31;
            *(float4*)&As[e][r][m4 * 4] =
                *(const float4*)(A + (size_t)e * NNSZ + (size_t)(n0 + r) * N + m0 + m4 * 4);
        }
    __syncthreads();

    for (int task = warp; task < 192; task += 8) {
        int plane = task >> 4, ktl = task & 15;
        int s = plane >> 2;
        const float* wv = wsm + (2 - s) * 16 + (plane & 3) * 4;
        int col = ktl * 8 + cl;
        float v0 = 0.f, v1 = 0.f, v2 = 0.f, v3 = 0.f;
        #pragma unroll
        for (int e = 0; e < 4; e++) {
            float we = wv[e];
            v0 = fmaf(we, As[e][g][col], v0);
            v1 = fmaf(we, As[e][g + 8][col], v1);
            v2 = fmaf(we, As[e][g][col + 4], v2);
            v3 = fmaf(we, As[e][g + 8][col + 4], v3);
        }
        float4 o = make_float4(to_tf32(v0), to_tf32(v1), to_tf32(v2), to_tf32(v3));
        size_t unit = (size_t)band * 256 + ch * 16 + ktl;
        *(float4*)(g_Am + (size_t)plane * NNSZ + unit * 128 + lane * 4) = o;
    }
}

// ---------------- matvec on raw A: vout_c = sum_i w[c,i] * (A_i @ vin_c) ----------------
__global__ void __launch_bounds__(256) k_matvec(const float* __restrict__ A, int stage) {
    const float* __restrict__ vin = (stage == 0) ? g_v1 : g_v2;
    float* __restrict__ vout = (stage == 0) ? g_v2 : g_v3;
    const float* wsrc = (stage == 0) ? g_fw[1] : g_fw[0];
    int n = blockIdx.x;
    int tid = threadIdx.x;
    float w[16];
    #pragma unroll
    for (int j = 0; j < 16; j++) w[j] = wsrc[j];
    float acc0 = 0.f, acc1 = 0.f, acc2 = 0.f, acc3 = 0.f;
    #pragma unroll
    for (int it = 0; it < (N / 4) / 256; it++) {
        int m4 = tid + it * 256;
        float4 vv0 = ((const float4*)(vin + 0 * N))[m4];
        float4 vv1 = ((const float4*)(vin + 1 * N))[m4];
        float4 vv2 = ((const float4*)(vin + 2 * N))[m4];
        float4 vv3 = ((const float4*)(vin + 3 * N))[m4];
        #pragma unroll
        for (int i = 0; i < 4; i++) {
            float4 a = ((const float4*)(A + (size_t)i * NNSZ + (size_t)n * N))[m4];
            float d0 = a.x * vv0.x + a.y * vv0.y + a.z * vv0.z + a.w * vv0.w;
            float d1 = a.x * vv1.x + a.y * vv1.y + a.z * vv1.z + a.w * vv1.w;
            float d2 = a.x * vv2.x + a.y * vv2.y + a.z * vv2.z + a.w * vv2.w;
            float d3 = a.x * vv3.x + a.y * vv3.y + a.z * vv3.z + a.w * vv3.w;
            acc0 = fmaf(w[0 * 4 + i], d0, acc0);
            acc1 = fmaf(w[1 * 4 + i], d1, acc1);
            acc2 = fmaf(w[2 * 4 + i], d2, acc2);
            acc3 = fmaf(w[3 * 4 + i], d3, acc3);
        }
    }
    #pragma unroll
    for (int off = 16; off > 0; off >>= 1) {
        acc0 += __shfl_down_sync(0xffffffffu, acc0, off);
        acc1 += __shfl_down_sync(0xffffffffu, acc1, off);
        acc2 += __shfl_down_sync(0xffffffffu, acc2, off);
        acc3 += __shfl_down_sync(0xffffffffu, acc3, off);
    }
    __shared__ float red[8][4];
    int lane = tid & 31, wid = tid >> 5;
    if (lane == 0) { red[wid][0] = acc0; red[wid][1] = acc1; red[wid][2] = acc2; red[wid][3] = acc3; }
    __syncthreads();
    if (tid < 4) {
        float s = 0.f;
        #pragma unroll
        for (int wv = 0; wv < 8; wv++) s += red[wv][tid];
        vout[tid * N + n] = s;
    }
}

// ---------------- d, Sp natural, SpB fragment-order ----------------
__global__ void __launch_bounds__(256) k_dSp_f() {
    __shared__ float sup[8][132];
    __shared__ float dsm[4][8];
    const int tid = threadIdx.x;
    const int k0 = blockIdx.x * 8;
    {
        int r = tid >> 5, f4 = (tid & 31) * 4;
        *(float4*)&sup[r][f4] = *(const float4*)(g_support + (size_t)(k0 + r) * F + f4);
    }
    if (tid < 32) {
        int c = tid >> 3, kk = tid & 7;
        float deg = g_v3[c * N + k0 + kk] + 1.0f;
        float d = (deg > 0.f) ? rsqrtf(deg) : 0.f;
        dsm[c][kk] = d;
        g_d[c * N + k0 + kk] = d;
    }
    __syncthreads();
    {
        int r = tid >> 5, f4 = (tid & 31) * 4;
        float4 s = *(float4*)&sup[r][f4];
        #pragma unroll
        for (int c = 0; c < 4; c++) {
            float d = dsm[c][r];
            float4 o = make_float4(d * s.x, d * s.y, d * s.z, d * s.w);
            *(float4*)(g_Sp + ((size_t)c * N + k0 + r) * F + f4) = o;
        }
    }
    {
        int nt = tid >> 5, l = tid & 31;
        int kl = l & 3, nl = nt * 16 + (l >> 2);
        #pragma unroll
        for (int c = 0; c < 4; c++) {
            float4 o;
            o.x = to_tf32(dsm[c][kl]     * sup[kl][nl]);
            o.y = to_tf32(dsm[c][kl + 4] * sup[kl + 4][nl]);
            o.z = to_tf32(dsm[c][kl]     * sup[kl][nl + 8]);
            o.w = to_tf32(dsm[c][kl + 4] * sup[kl + 4][nl + 8]);
            *(float4*)(g_SpB + (size_t)c * NFSZ + ((size_t)blockIdx.x * 8 + nt) * 128 + l * 4) = o;
        }
    }
}

// ---------------- main GEMM: 512 threads, warp tile 16x32, direct-LDG mma tf32 ----------------
__global__ void __launch_bounds__(512) k_gemm_f(const float* __restrict__ bias,
                                                float* __restrict__ out, int stage) {
    __shared__ float sm[64][132];
    const int tid = threadIdx.x, lane = tid & 31, warp = tid >> 5;   // 16 warps
    const int wm = warp >> 2, wn = warp & 3;       // 4 x 4
    const int c = blockIdx.y;
    const int n0 = blockIdx.x * 64;

    const float* __restrict__ Af = g_Am + (size_t)(stage * 4 + c) * NNSZ;
    const float* __restrict__ Bfp = ((stage == 0) ? g_SpB : (stage == 1) ? g_T0B : g_T1B)
                                    + (size_t)c * NFSZ;
    const uint4* __restrict__ Abase = (const uint4*)Af
        + ((size_t)(blockIdx.x * 4 + wm) * 256) * 32 + lane;
    const uint4* __restrict__ Bbase = (const uint4*)Bfp + (size_t)(wn * 2) * 32 + lane;

    float acc[4][4];
    #pragma unroll
    for (int j = 0; j < 4; j++)
        #pragma unroll
        for (int q = 0; q < 4; q++) acc[j][q] = 0.f;

    uint4 ab[4], bb[4][2];
    #pragma unroll
    for (int p = 0; p < 3; p++) {
        ab[p] = Abase[(size_t)p * 32];
        bb[p][0] = Bbase[(size_t)p * 256];
        bb[p][1] = Bbase[(size_t)p * 256 + 32];
    }

    for (int kt4 = 0; kt4 < 64; kt4++) {
        #pragma unroll
        for (int s = 0; s < 4; s++) {
            const int kt = kt4 * 4 + s;
            const int slot = kt & 3;
            const int pf = kt + 3;
            if (pf < 256) {
                const int ps = pf & 3;
                ab[ps] = Abase[(size_t)pf * 32];
                bb[ps][0] = Bbase[(size_t)pf * 256];
                bb[ps][1] = Bbase[(size_t)pf * 256 + 32];
            }
            uint4 a = ab[slot];
            #pragma unroll
            for (int u = 0; u < 2; u++) {
                uint4 b = bb[slot][u];
                mma_tf32(acc[u * 2][0], acc[u * 2][1], acc[u * 2][2], acc[u * 2][3],
                         a.x, a.y, a.z, a.w, b.x, b.y);
                mma_tf32(acc[u * 2 + 1][0], acc[u * 2 + 1][1], acc[u * 2 + 1][2], acc[u * 2 + 1][3],
                         a.x, a.y, a.z, a.w, b.z, b.w);
            }
        }
    }

    {
        const int g = lane >> 2, th = lane & 3;
        #pragma unroll
        for (int j = 0; j < 4; j++) {
            int row = wm * 16 + g;
            int col = wn * 32 + (j >> 1) * 16 + (j & 1) * 8 + 2 * th;
            sm[row][col] = acc[j][0];
            sm[row][col + 1] = acc[j][1];
            sm[row + 8][col] = acc[j][2];
            sm[row + 8][col + 1] = acc[j][3];
        }
    }
    __syncthreads();

    if (stage < 2) {
        float* __restrict__ Bout = ((stage == 0) ? g_T0B : g_T1B) + (size_t)c * NFSZ;
        const int ku = warp >> 1;
        const int nu0 = (warp & 1) * 4;
        const int ka = ku * 8 + (lane & 3);
        const int nloc = lane >> 2;
        #pragma unroll
        for (int q = 0; q < 4; q++) {
            int nu = nu0 + q;
            int nl = nu * 16 + nloc;
            float4 o;
            o.x = to_tf32(sm[ka][nl]);
            o.y = to_tf32(sm[ka + 4][nl]);
            o.z = to_tf32(sm[ka][nl + 8]);
            o.w = to_tf32(sm[ka + 4][nl + 8]);
            *(float4*)(Bout + ((size_t)(blockIdx.x * 8 + ku) * 8 + nu) * 128 + lane * 4) = o;
        }
    } else {
        const int r = tid >> 3;
        const int fc = (tid & 7) * 16;
        const int node = n0 + r;
        const float dd = g_d[c * N + node];
        const float* sp = g_Sp + ((size_t)(c * N + node)) * F;
        float* op = out + (size_t)node * (C * F) + c * F;
        #pragma unroll
        for (int j0 = 0; j0 < 16; j0 += 4) {
            float4 a4 = *(float4*)&sm[r][fc + j0];
            float4 s4 = *(const float4*)(sp + fc + j0);
            float4 b4 = *(const float4*)(bias + fc + j0);
            float4 o;
            o.x = fmaxf(dd * (a4.x + s4.x) + b4.x, 0.f);
            o.y = fmaxf(dd * (a4.y + s4.y) + b4.y, 0.f);
            o.z = fmaxf(dd * (a4.z + s4.z) + b4.z, 0.f);
            o.w = fmaxf(dd * (a4.w + s4.w) + b4.w, 0.f);
            *(float4*)(op + fc + j0) = o;
        }
    }
}

// ---------------- launcher: fork-join overlap of premix (A) and degree chain (B) ----------------
extern "C" void kernel_launch(void* const* d_in, const int* in_sizes, int n_in,
                              void* d_out, int out_size) {
    const float* A  = (const float*)d_in[0];   // [E,N,N]
    const float* X  = (const float*)d_in[1];   // [N,WIN]
    const float* w1 = (const float*)d_in[2];   // [C,E]
    const float* w2 = (const float*)d_in[3];   // [C,E]
    const float* w3 = (const float*)d_in[4];   // [C,C]
    const float* gw = (const float*)d_in[5];   // [WIN,F]
    const float* gb = (const float*)d_in[6];   // [F]
    float* out = (float*)d_out;                // [N, C*F]

    // lazy, idempotent host-side setup (first call happens outside graph capture)
    static cudaStream_t s_side = nullptr;
    static cudaEvent_t ev_fork = nullptr, ev_join = nullptr;
    if (s_side == nullptr) {
        cudaStreamCreateWithFlags(&s_side, cudaStreamNonBlocking);
        cudaEventCreateWithFlags(&ev_fork, cudaEventDisableTiming);
        cudaEventCreateWithFlags(&ev_join, cudaEventDisableTiming);
    }

    k_softmax<<<1, 32>>>(w1, w2, w3);

    // fork: chain B on side stream (independent of premix output)
    cudaEventRecord(ev_fork, 0);
    cudaStreamWaitEvent(s_side, ev_fork, 0);
    k_rowsum_mix<<<N, 256, 0, s_side>>>(A);            // v1 = Hc @ 1
    k_matvec<<<N, 256, 0, s_side>>>(A, 0);             // v2 = Hb @ v1
    k_matvec<<<N, 256, 0, s_side>>>(A, 1);             // v3 = Ha @ v2
    k_support<<<N / 32, 256, 0, s_side>>>(X, gw);      // support = X @ gcn_w
    k_dSp_f<<<N / 8, 256, 0, s_side>>>();              // d, Sp, SpB
    cudaEventRecord(ev_join, s_side);

    // chain A on main stream
    k_premix_f<<<dim3(16, 128), 256>>>(A);             // 12 frag-order tf32 planes

    // join, then the three tensor GEMM stages
    cudaStreamWaitEvent(0, ev_join, 0);
    k_gemm_f<<<dim3(N / 64, C), 512>>>(gb, out, 0);    // T0B
    k_gemm_f<<<dim3(N / 64, C), 512>>>(gb, out, 1);    // T1B
    k_gemm_f<<<dim3(N / 64, C), 512>>>(gb, out, 2);    // out = relu(d*(Ha@T1+Sp)+b)
}